// round 10
// baseline (speedup 1.0000x reference)
#include <cuda_runtime.h>
#include <cuda_bf16.h>
#include <cstdint>

#define NB 4
#define NN 16384
#define NEG 131072
#define NH 4
#define NDK 32
#define NDM 128
#define EPB 8  // rows per warp block in scalar gemm kernels

#define TILE_M 128
#define NTILES (NB * NEG / TILE_M)  // 4096

// tcgen05 only legal in arch-specific (sm_103a) device compilation passes.
#if defined(__CUDA_ARCH__) && (__CUDA_ARCH__ == 1030) && \
    (defined(__CUDA_ARCH_FEAT_SM103_ALL) || defined(__CUDA_ARCH_SPECIFIC__))
#define HAS_TCGEN05 1
#else
#define HAS_TCGEN05 0
#endif

// ---------------- device scratch (no allocs allowed) ----------------
__device__ float g_Q[NB * NN * NDM];
__device__ float g_K[NB * NN * NDM];
__device__ float g_V[NB * NN * NDM];
__device__ float g_num[NB * NN * NDM];
__device__ float g_den[NB * NN * NH];

// ---------------- packed f32x2 helpers ----------------
__device__ __forceinline__ unsigned long long pack2(float a, float b) {
    unsigned long long r;
    asm("mov.b64 %0, {%1,%2};" : "=l"(r) : "f"(a), "f"(b));
    return r;
}
__device__ __forceinline__ void unpack2(unsigned long long v, float& a, float& b) {
    asm("mov.b64 {%0,%1}, %2;" : "=f"(a), "=f"(b) : "l"(v));
}
__device__ __forceinline__ unsigned long long fma2(unsigned long long a, unsigned long long b,
                                                   unsigned long long c) {
    unsigned long long r;
    asm("fma.rn.f32x2 %0, %1, %2, %3;" : "=l"(r) : "l"(a), "l"(b), "l"(c));
    return r;
}

__device__ __forceinline__ float wsum(float v) {
#pragma unroll
    for (int o = 16; o; o >>= 1) v += __shfl_xor_sync(0xffffffffu, v, o);
    return v;
}

// ---------------- edge tc kernel smem layout ----------------
// B split (hi/lo) shared; A split per group; control + per-group staging.
#define SM_B_HI 0
#define SM_B_LO 32768
#define SM_A_HI_G(g) (65536 + (g) * 65536)
#define SM_A_LO_G(g) (98304 + (g) * 65536)
#define SM_TPTR 196608
#define SM_MBAR 196624                     // 4 mbarriers (g*16 + slot*8)
#define SM_PART 196672                     // float4[2][128]
#define SM_ATTN (SM_PART + 4096)           // float4[2][128]
#define SM_ROWS (SM_ATTN + 4096)           // int2[2][128]
#define SMEM_EDGE_BYTES (SM_ROWS + 2048)   // ~203KB

#if HAS_TCGEN05
// ---------------- tcgen05 / mbarrier PTX helpers (arch-specific only) ----------------
__device__ __forceinline__ uint32_t smem_u32(const void* p) {
    uint32_t a;
    asm("{ .reg .u64 t; cvta.to.shared.u64 t, %1; cvt.u32.u64 %0, t; }" : "=r"(a) : "l"(p));
    return a;
}
__device__ __forceinline__ uint32_t elect_one_pred() {
    uint32_t pred;
    asm volatile(
        "{\n\t.reg .pred p;\n\telect.sync _|p, 0xFFFFFFFF;\n\tselp.b32 %0, 1, 0, p;\n\t}"
        : "=r"(pred));
    return pred;
}

#define TCG_ALLOC(smem_addr, ncols) \
    asm volatile("tcgen05.alloc.cta_group::1.sync.aligned.shared::cta.b32 [%0], %1;" \
                 :: "r"((uint32_t)(smem_addr)), "r"((uint32_t)(ncols)) : "memory")
#define TCG_DEALLOC(tmem, ncols) \
    asm volatile("tcgen05.dealloc.cta_group::1.sync.aligned.b32 %0, %1;" :: "r"(tmem), "r"((uint32_t)(ncols)))
#define TCG_COMMIT(mbar) \
    asm volatile("tcgen05.commit.cta_group::1.mbarrier::arrive::one.shared::cluster.b64 [%0];" \
                 :: "r"((uint32_t)(mbar)) : "memory")
#define TCG_WAIT_LD() asm volatile("tcgen05.wait::ld.sync.aligned;" ::: "memory")
#define TCG_FENCE_AFTER() asm volatile("tcgen05.fence::after_thread_sync;" ::: "memory")
#define FENCE_ASYNC_SHARED() asm volatile("fence.proxy.async.shared::cta;" ::: "memory")

#define MBAR_INIT(mbar, cnt) \
    asm volatile("mbarrier.init.shared.b64 [%0], %1;" :: "r"((uint32_t)(mbar)), "r"((uint32_t)(cnt)) : "memory")

#define MBAR_WAIT_PARITY(mbar, parity) do {                                              \
    uint32_t _m = (uint32_t)(mbar);                                                      \
    uint32_t _p = (uint32_t)(parity);                                                    \
    asm volatile(                                                                        \
        "{\n\t.reg .pred P1;\n\t"                                                        \
        "WAIT_LOOP_%=:\n\t"                                                              \
        "mbarrier.try_wait.parity.acquire.cta.shared::cta.b64 P1, [%0], %1, 0x989680;\n\t" \
        "@P1 bra.uni WAIT_DONE_%=;\n\t"                                                  \
        "bra.uni WAIT_LOOP_%=;\n\t"                                                      \
        "WAIT_DONE_%=:\n\t}"                                                             \
        :: "r"(_m), "r"(_p) : "memory");                                                 \
} while (0)

#define BAR_GRP(id) asm volatile("bar.sync %0, 256;" :: "r"(id) : "memory")

#define TCG_LD_X32(r, addr)                                                              \
    asm volatile(                                                                        \
        "tcgen05.ld.sync.aligned.32x32b.x32.b32 "                                        \
        "{%0, %1, %2, %3, %4, %5, %6, %7, "                                              \
        " %8, %9, %10, %11, %12, %13, %14, %15, "                                        \
        " %16, %17, %18, %19, %20, %21, %22, %23, "                                      \
        " %24, %25, %26, %27, %28, %29, %30, %31}, [%32];"                               \
        : "=r"((r)[0]),  "=r"((r)[1]),  "=r"((r)[2]),  "=r"((r)[3]),                     \
          "=r"((r)[4]),  "=r"((r)[5]),  "=r"((r)[6]),  "=r"((r)[7]),                     \
          "=r"((r)[8]),  "=r"((r)[9]),  "=r"((r)[10]), "=r"((r)[11]),                    \
          "=r"((r)[12]), "=r"((r)[13]), "=r"((r)[14]), "=r"((r)[15]),                    \
          "=r"((r)[16]), "=r"((r)[17]), "=r"((r)[18]), "=r"((r)[19]),                    \
          "=r"((r)[20]), "=r"((r)[21]), "=r"((r)[22]), "=r"((r)[23]),                    \
          "=r"((r)[24]), "=r"((r)[25]), "=r"((r)[26]), "=r"((r)[27]),                    \
          "=r"((r)[28]), "=r"((r)[29]), "=r"((r)[30]), "=r"((r)[31])                     \
        : "r"(addr))

__device__ __forceinline__ void mma_f16_ss(uint32_t d, uint64_t ad, uint64_t bd,
                                           uint32_t idesc, uint32_t en) {
    asm volatile(
        "{\n\t.reg .pred p;\n\tsetp.ne.u32 p, %5, 0;\n\t"
        "tcgen05.mma.cta_group::1.kind::f16 [%0], %1, %2, %3, {%4, %4, %4, %4}, p;\n\t}"
        :: "r"(d), "l"(ad), "l"(bd), "r"(idesc), "r"(0u), "r"(en) : "memory");
}

__device__ __forceinline__ void red_add_v4(float* p, float a, float b, float c, float d) {
    asm volatile("red.global.add.v4.f32 [%0], {%1, %2, %3, %4};"
                 :: "l"(p), "f"(a), "f"(b), "f"(c), "f"(d) : "memory");
}

// blocked SW128 atom layout for 128x128 bf16 tile (atom = 8 rows x 64 cols = 1024B,
// 16 atom-rows x 2 atom-cols, atom_off = ar + ac*16) — extension of test_mma_iter.
__device__ __forceinline__ uint32_t ab_off(int row, int col) {
    uint32_t byte = (uint32_t)(((row >> 3) + (col >> 6) * 16) * 1024 + (row & 7) * 128 + (col & 63) * 2);
    return byte ^ ((byte >> 3) & 0x70);
}
__device__ __forceinline__ uint64_t mk_desc(uint32_t a) {
    return (uint64_t(2) << 61) | (uint64_t(1) << 46) | (uint64_t(64) << 32) |
           (uint64_t(1) << 16) | ((a >> 4) & 0x3FFF);
}

// idesc: F32 accum, BF16 a/b, N=128, M=128 (cg1)
#define MMA_IDESC 0x8200490u

__device__ __forceinline__ unsigned short bf16b(__nv_bfloat16 h) {
    return __bfloat16_as_ushort(h);
}

__device__ __forceinline__ void load_A_tile(const float* __restrict__ ef, long long rowbase,
                                            char* sm, int a_hi, int a_lo, int t0, int stride) {
    for (int i = t0; i < 4096; i += stride) {
        int r = i >> 5;
        int c4 = (i & 31) << 2;
        float4 x = *reinterpret_cast<const float4*>(ef + (rowbase + r) * NDM + c4);
        __nv_bfloat16 hx = __float2bfloat16(x.x), hy = __float2bfloat16(x.y);
        __nv_bfloat16 hz = __float2bfloat16(x.z), hw = __float2bfloat16(x.w);
        __nv_bfloat16 lx = __float2bfloat16(x.x - __bfloat162float(hx));
        __nv_bfloat16 ly = __float2bfloat16(x.y - __bfloat162float(hy));
        __nv_bfloat16 lz = __float2bfloat16(x.z - __bfloat162float(hz));
        __nv_bfloat16 lw = __float2bfloat16(x.w - __bfloat162float(hw));
        uint32_t off = ab_off(r, c4);
        uint2 hv = make_uint2((uint32_t)bf16b(hx) | ((uint32_t)bf16b(hy) << 16),
                              (uint32_t)bf16b(hz) | ((uint32_t)bf16b(hw) << 16));
        uint2 lv = make_uint2((uint32_t)bf16b(lx) | ((uint32_t)bf16b(ly) << 16),
                              (uint32_t)bf16b(lz) | ((uint32_t)bf16b(lw) << 16));
        *reinterpret_cast<uint2*>(sm + a_hi + off) = hv;
        *reinterpret_cast<uint2*>(sm + a_lo + off) = lv;
    }
}

__device__ __forceinline__ void issue_mma_tile(uint32_t d_tmem, uint32_t smb,
                                               int a_hi, int a_lo, uint32_t mbar) {
    uint64_t ah = mk_desc(smb + a_hi), al = mk_desc(smb + a_lo);
    uint64_t bh = mk_desc(smb + SM_B_HI), bl = mk_desc(smb + SM_B_LO);
    uint64_t Ad[3] = {ah, ah, al};
    uint64_t Bd[3] = {bh, bl, bh};
#pragma unroll
    for (int p = 0; p < 3; ++p) {
#pragma unroll
        for (int s = 0; s < 8; ++s) {
            uint32_t off = (s < 4) ? (uint32_t)(2 * s) : (uint32_t)(1024 + 2 * (s - 4));
            mma_f16_ss(d_tmem, Ad[p] + off, Bd[p] + off, MMA_IDESC, !(p == 0 && s == 0));
        }
    }
    TCG_COMMIT(mbar);
}
#endif  // HAS_TCGEN05

// ---------------- edge tensor-core kernel (active only in sm_103a-specific cubin) ----------------
// Two independent tile pipelines per CTA (warp groups of 8), each with its own
// TMEM D double-buffer, A smem buffer, mbarrier pair, and named barrier.
__global__ __launch_bounds__(512, 1) void edge_tc_kernel(const int* __restrict__ eidx,
                                                         const float* __restrict__ ef,
                                                         const float* __restrict__ WE,
                                                         float* __restrict__ attn_out) {
#if HAS_TCGEN05
    extern __shared__ char sm[];
    uint32_t smb = smem_u32(sm);
    const int tid = threadIdx.x, wid = tid >> 5, lane = tid & 31;
    const int grp = wid >> 3;          // 0 or 1: independent tile pipeline
    const int gwid = wid & 7;          // warp within group
    const int gtid = tid & 255;        // thread within group
    const int barid = 1 + grp;
    const float scale = 0.1767766952966369f;  // 1/sqrt(32)

    const int a_hi = SM_A_HI_G(grp), a_lo = SM_A_LO_G(grp);

    if (wid == 0) TCG_ALLOC(smb + SM_TPTR, 512);

    // stage B = W_E, transposed to [n][k], cols head-permuted n = d*4+h <- h*32+d, split bf16
    for (int i = tid; i < NDM * NDM; i += 512) {
        int n = i >> 7, k = i & 127;
        float w = WE[k * NDM + ((n & 3) * NDK + (n >> 2))];
        __nv_bfloat16 h = __float2bfloat16(w);
        __nv_bfloat16 l = __float2bfloat16(w - __bfloat162float(h));
        uint32_t off = ab_off(n, k);
        *reinterpret_cast<unsigned short*>(sm + SM_B_HI + off) = bf16b(h);
        *reinterpret_cast<unsigned short*>(sm + SM_B_LO + off) = bf16b(l);
    }
    if (tid < 4) MBAR_INIT(smb + SM_MBAR + tid * 8, 1);
    __syncthreads();

    uint32_t tmem;
    asm volatile("ld.shared.b32 %0, [%1];" : "=r"(tmem) : "r"(smb + SM_TPTR));

    const int t0g = blockIdx.x + grp * gridDim.x;
    const int tstep = 2 * gridDim.x;

    // prologue: each group stages A for its first tile, issues MMA -> its slot 0
    if (t0g < NTILES) {
        long long rb = (long long)(t0g >> 10) * NEG + (long long)(t0g & 1023) * TILE_M;
        load_A_tile(ef, rb, sm, a_hi, a_lo, gtid, 256);
    }
    FENCE_ASYNC_SHARED();
    BAR_GRP(barid);
    if (t0g < NTILES && gwid == 0 && elect_one_pred())
        issue_mma_tile(tmem + (uint32_t)(grp * 256), smb, a_hi, a_lo, smb + SM_MBAR + grp * 16);

    int ph0 = 0, ph1 = 0;
    int i = 0;
    for (int t = t0g; t < NTILES; t += tstep, ++i) {
        const int slot = i & 1;
        if (slot == 0) { MBAR_WAIT_PARITY(smb + SM_MBAR + grp * 16, ph0); ph0 ^= 1; }
        else           { MBAR_WAIT_PARITY(smb + SM_MBAR + grp * 16 + 8, ph1); ph1 ^= 1; }
        TCG_FENCE_AFTER();

        const int b = t >> 10;
        const int e0 = (t & 1023) * TILE_M;
        const int tn = t + tstep;

        // ---- stage A(next) while D(t) is consumed below; A buffer free since MMA(t) done ----
        if (tn < NTILES) {
            long long rb = (long long)(tn >> 10) * NEG + (long long)(tn & 1023) * TILE_M;
            load_A_tile(ef, rb, sm, a_hi, a_lo, gtid, 256);
        }
        FENCE_ASYNC_SHARED();
        BAR_GRP(barid);
        if (tn < NTILES && gwid == 0 && elect_one_pred())
            issue_mma_tile(tmem + (uint32_t)(grp * 256 + ((i + 1) & 1) * 128), smb, a_hi, a_lo,
                           smb + SM_MBAR + grp * 16 + ((i + 1) & 1) * 8);

        // ---- score phase: warps 0-3 of group cols [0,64), warps 4-7 cols [64,128) ----
        float s0 = 0.f, s1 = 0.f, s2 = 0.f, s3 = 0.f;
        int qrow = 0;
        {
            const uint32_t Dcur = tmem + (uint32_t)(grp * 256 + slot * 128);
            const int sub = gwid & 3, half = gwid >> 2;
            const int m = sub * 32 + lane;
            const int e = e0 + m;
            const int src = eidx[(b * 2) * NEG + e];
            const int tgt = eidx[(b * 2 + 1) * NEG + e];
            qrow = b * NN + src;
            const int krow = b * NN + tgt;
#pragma unroll 1
            for (int c = 0; c < 2; ++c) {
                const int col = half * 64 + c * 32;
                uint32_t rE[32];
                TCG_LD_X32(rE, Dcur + (uint32_t)col);
                TCG_WAIT_LD();
                const float4* qp = reinterpret_cast<const float4*>(g_Q + (long long)qrow * NDM + col);
                const float4* kp = reinterpret_cast<const float4*>(g_K + (long long)krow * NDM + col);
#pragma unroll
                for (int j = 0; j < 8; ++j) {
                    float4 q4 = qp[j], k4 = kp[j];
                    s0 += q4.x * k4.x * __uint_as_float(rE[4 * j + 0]);
                    s1 += q4.y * k4.y * __uint_as_float(rE[4 * j + 1]);
                    s2 += q4.z * k4.z * __uint_as_float(rE[4 * j + 2]);
                    s3 += q4.w * k4.w * __uint_as_float(rE[4 * j + 3]);
                }
            }
            if (half)
                reinterpret_cast<float4*>(sm + SM_PART + grp * 2048)[m] = make_float4(s0, s1, s2, s3);
            else
                reinterpret_cast<int2*>(sm + SM_ROWS + grp * 1024)[m] = make_int2(qrow, krow);
        }
        BAR_GRP(barid);

        // ---- finalize: warps 0-3 of group ----
        if (gwid < 4) {
            const int m = gwid * 32 + lane;
            float4 p = reinterpret_cast<const float4*>(sm + SM_PART + grp * 2048)[m];
            s0 += p.x; s1 += p.y; s2 += p.z; s3 += p.w;
            float a0 = __expf(fminf(fmaxf(s0 * scale, -5.f), 5.f));
            float a1 = __expf(fminf(fmaxf(s1 * scale, -5.f), 5.f));
            float a2 = __expf(fminf(fmaxf(s2 * scale, -5.f), 5.f));
            float a3 = __expf(fminf(fmaxf(s3 * scale, -5.f), 5.f));

            red_add_v4(g_den + (long long)qrow * NH, a0, a1, a2, a3);
            if (b == NB - 1) {
                const int e = e0 + m;
                attn_out[e] = a0;
                attn_out[NEG + e] = a1;
                attn_out[2 * NEG + e] = a2;
                attn_out[3 * NEG + e] = a3;
            }
            reinterpret_cast<float4*>(sm + SM_ATTN + grp * 2048)[m] = make_float4(a0, a1, a2, a3);
        }
        BAR_GRP(barid);

        // ---- scatter: 8 warps of group, 16 edges each, one float4 per lane per edge ----
#pragma unroll 4
        for (int k = 0; k < 16; ++k) {
            const int m = gwid * 16 + k;
            float4 a4 = reinterpret_cast<const float4*>(sm + SM_ATTN + grp * 2048)[m];
            int2 rw = reinterpret_cast<const int2*>(sm + SM_ROWS + grp * 1024)[m];
            float4 v4 = reinterpret_cast<const float4*>(g_V + (long long)rw.y * NDM)[lane];
            red_add_v4(g_num + (long long)rw.x * NDM + 4 * lane,
                       a4.x * v4.x, a4.y * v4.y, a4.z * v4.z, a4.w * v4.w);
        }
    }

    __syncthreads();
    if (wid == 0) TCG_DEALLOC(tmem, 512);
#else
    // generic cubin: no-op (scalar edge_kernel does the work)
    (void)eidx; (void)ef; (void)WE; (void)attn_out;
#endif
}

// ---------------- scalar warp GEMM pieces ----------------
__device__ __forceinline__ void warp_block_gemm8(const float* __restrict__ xs,
                                                 const float* __restrict__ Ws, int lane,
                                                 float4* __restrict__ out) {
    unsigned long long a01[EPB], a23[EPB];
#pragma unroll
    for (int e = 0; e < EPB; ++e) { a01[e] = 0ull; a23[e] = 0ull; }
#pragma unroll 2
    for (int g = 0; g < 32; ++g) {
        const float* wp = Ws + (4 * g) * NDM + 4 * lane;
        float4 w0 = *reinterpret_cast<const float4*>(wp);
        float4 w1 = *reinterpret_cast<const float4*>(wp + NDM);
        float4 w2 = *reinterpret_cast<const float4*>(wp + 2 * NDM);
        float4 w3 = *reinterpret_cast<const float4*>(wp + 3 * NDM);
        unsigned long long w0a = pack2(w0.x, w0.y), w0b = pack2(w0.z, w0.w);
        unsigned long long w1a = pack2(w1.x, w1.y), w1b = pack2(w1.z, w1.w);
        unsigned long long w2a = pack2(w2.x, w2.y), w2b = pack2(w2.z, w2.w);
        unsigned long long w3a = pack2(w3.x, w3.y), w3b = pack2(w3.z, w3.w);
#pragma unroll
        for (int e = 0; e < EPB; ++e) {
            float4 x = *reinterpret_cast<const float4*>(xs + e * NDM + 4 * g);
            unsigned long long xx;
            xx = pack2(x.x, x.x); a01[e] = fma2(xx, w0a, a01[e]); a23[e] = fma2(xx, w0b, a23[e]);
            xx = pack2(x.y, x.y); a01[e] = fma2(xx, w1a, a01[e]); a23[e] = fma2(xx, w1b, a23[e]);
            xx = pack2(x.z, x.z); a01[e] = fma2(xx, w2a, a01[e]); a23[e] = fma2(xx, w2b, a23[e]);
            xx = pack2(x.w, x.w); a01[e] = fma2(xx, w3a, a01[e]); a23[e] = fma2(xx, w3b, a23[e]);
        }
    }
#pragma unroll
    for (int e = 0; e < EPB; ++e) {
        unpack2(a01[e], out[e].x, out[e].y);
        unpack2(a23[e], out[e].z, out[e].w);
    }
}

__device__ __forceinline__ void load_W_headperm(const float* __restrict__ W, float* Wr) {
    for (int idx = threadIdx.x; idx < NDM * NDM; idx += blockDim.x) {
        int c = idx & (NDM - 1);
        int d = c >> 2, h = c & 3;
        Wr[idx] = W[(idx - c) + h * NDK + d];
    }
}

#define SMEM_FLOATS (NDM * NDM + 8 * EPB * NDM)

// ---------------- scalar edge kernel (active only in generic cubin) ----------------
__global__ __launch_bounds__(256, 2) void edge_kernel(const int* __restrict__ eidx,
                                                      const float* __restrict__ ef,
                                                      const float* __restrict__ WE,
                                                      float* __restrict__ attn_out) {
#if HAS_TCGEN05
    (void)eidx; (void)ef; (void)WE; (void)attn_out;  // tc kernel does the work
#else
    extern __shared__ float smf[];
    float* Wr = smf;
    load_W_headperm(WE, Wr);
    __syncthreads();

    const int lane = threadIdx.x & 31;
    const int warp = threadIdx.x >> 5;
    float* xs = smf + NDM * NDM + warp * EPB * NDM;
    int gw = blockIdx.x * (blockDim.x >> 5) + warp;
    int nw = gridDim.x * (blockDim.x >> 5);
    const float scale = 0.1767766952966369f;  // 1/sqrt(32)

    const int ngroups = NB * NEG / EPB;
    const int gpb = NEG / EPB;

    for (int gi = gw; gi < ngroups; gi += nw) {
        int b = gi / gpb;
        int e0 = (gi - b * gpb) * EPB;

        int src_l = 0, tgt_l = 0;
        if (lane < EPB) {
            src_l = eidx[(b * 2) * NEG + e0 + lane];
            tgt_l = eidx[(b * 2 + 1) * NEG + e0 + lane];
        }

        long long t0 = (long long)b * NEG + e0;
#pragma unroll
        for (int e = 0; e < EPB; ++e) {
            float4 x4 = *reinterpret_cast<const float4*>(ef + (t0 + e) * NDM + 4 * lane);
            *reinterpret_cast<float4*>(xs + e * NDM + 4 * lane) = x4;
        }
        __syncwarp();

        float4 Ev[EPB];
        warp_block_gemm8(xs, Wr, lane, Ev);

#pragma unroll
        for (int c = 0; c < 2; ++c) {
            float4 q[4], k4[4], v4[4];
            int qr[4];
#pragma unroll
            for (int ii = 0; ii < 4; ++ii) {
                int e = c * 4 + ii;
                int src = __shfl_sync(0xffffffffu, src_l, e);
                int tgt = __shfl_sync(0xffffffffu, tgt_l, e);
                qr[ii] = b * NN + src;
                int kr = b * NN + tgt;
                q[ii]  = *reinterpret_cast<const float4*>(g_Q + (long long)qr[ii] * NDM + 4 * lane);
                k4[ii] = *reinterpret_cast<const float4*>(g_K + (long long)kr * NDM + 4 * lane);
                v4[ii] = *reinterpret_cast<const float4*>(g_V + (long long)kr * NDM + 4 * lane);
            }
#pragma unroll
            for (int ii = 0; ii < 4; ++ii) {
                int e = c * 4 + ii;
                float4 E = Ev[e];
                float p0 = wsum(q[ii].x * k4[ii].x * E.x);
                float p1 = wsum(q[ii].y * k4[ii].y * E.y);
                float p2 = wsum(q[ii].z * k4[ii].z * E.z);
                float p3 = wsum(q[ii].w * k4[ii].w * E.w);

                float a0 = __expf(fminf(fmaxf(p0 * scale, -5.f), 5.f));
                float a1 = __expf(fminf(fmaxf(p1 * scale, -5.f), 5.f));
                float a2 = __expf(fminf(fmaxf(p2 * scale, -5.f), 5.f));
                float a3 = __expf(fminf(fmaxf(p3 * scale, -5.f), 5.f));

                float* np = g_num + (long long)qr[ii] * NDM + 4 * lane;
                atomicAdd(np + 0, a0 * v4[ii].x);
                atomicAdd(np + 1, a1 * v4[ii].y);
                atomicAdd(np + 2, a2 * v4[ii].z);
                atomicAdd(np + 3, a3 * v4[ii].w);
                if (lane < 4) {
                    float aa = lane == 0 ? a0 : (lane == 1 ? a1 : (lane == 2 ? a2 : a3));
                    atomicAdd(g_den + qr[ii] * NH + lane, aa);
                    if (b == NB - 1) attn_out[(long long)lane * NEG + e0 + e] = aa;
                }
            }
        }
        __syncwarp();
    }
#endif
}

// ---------------- kernel 1: projections, 8 rows per warp ----------------
__global__ __launch_bounds__(256, 2) void proj_kernel(const float* __restrict__ X,
                                                      const float* __restrict__ W,
                                                      float* __restrict__ Y, int nrows) {
    extern __shared__ float smf[];
    float* Wr = smf;
    load_W_headperm(W, Wr);
    __syncthreads();

    const int lane = threadIdx.x & 31;
    const int warp = threadIdx.x >> 5;
    float* xs = smf + NDM * NDM + warp * EPB * NDM;
    int gw = blockIdx.x * (blockDim.x >> 5) + warp;
    int nw = gridDim.x * (blockDim.x >> 5);
    const int ngroups = nrows / EPB;

    for (int gi = gw; gi < ngroups; gi += nw) {
        long long r0 = (long long)gi * EPB;
#pragma unroll
        for (int e = 0; e < EPB; ++e) {
            float4 x4 = *reinterpret_cast<const float4*>(X + (r0 + e) * NDM + 4 * lane);
            *reinterpret_cast<float4*>(xs + e * NDM + 4 * lane) = x4;
        }
        __syncwarp();
        float4 y[EPB];
        warp_block_gemm8(xs, Wr, lane, y);
#pragma unroll
        for (int e = 0; e < EPB; ++e)
            *reinterpret_cast<float4*>(Y + (r0 + e) * NDM + 4 * lane) = y[e];
        __syncwarp();
    }
}

// ---------------- kernel 3: num/den -> @W_fc -> +residual -> layernorm ----------------
__global__ __launch_bounds__(256, 2) void finalize_kernel(const float* __restrict__ residual,
                                                          const float* __restrict__ Wfc,
                                                          const float* __restrict__ gamma,
                                                          const float* __restrict__ beta,
                                                          float* __restrict__ out) {
    extern __shared__ float smf[];
    float* Wr = smf;
    for (int idx = threadIdx.x; idx < NDM * NDM; idx += blockDim.x) {
        int jp = idx >> 7, m = idx & 127;
        int srow = (jp & 3) * NDK + (jp >> 2);
        Wr[idx] = Wfc[srow * NDM + m];
    }
    __syncthreads();

    const int lane = threadIdx.x & 31;
    const int warp = threadIdx.x >> 5;
    float* xs = smf + NDM * NDM + warp * EPB * NDM;
    int gw = blockIdx.x * (blockDim.x >> 5) + warp;
    int nw = gridDim.x * (blockDim.x >> 5);

    float4 g4 = *reinterpret_cast<const float4*>(gamma + 4 * lane);
    float4 b4 = *reinterpret_cast<const float4*>(beta + 4 * lane);
    const int ngroups = NB * NN / EPB;

    for (int gi = gw; gi < ngroups; gi += nw) {
        long long r0 = (long long)gi * EPB;
#pragma unroll
        for (int e = 0; e < EPB; ++e) {
            float4 num4 = *reinterpret_cast<const float4*>(g_num + (r0 + e) * NDM + 4 * lane);
            float4 den4 = *reinterpret_cast<const float4*>(g_den + (r0 + e) * NH);
            float4 o;
            o.x = num4.x / (den4.x + 1e-8f);
            o.y = num4.y / (den4.y + 1e-8f);
            o.z = num4.z / (den4.z + 1e-8f);
            o.w = num4.w / (den4.w + 1e-8f);
            *reinterpret_cast<float4*>(xs + e * NDM + 4 * lane) = o;
        }
        __syncwarp();

        float4 y[EPB];
        warp_block_gemm8(xs, Wr, lane, y);

#pragma unroll
        for (int e = 0; e < EPB; ++e) {
            float4 res = *reinterpret_cast<const float4*>(residual + (r0 + e) * NDM + 4 * lane);
            float4 v = y[e];
            v.x += res.x; v.y += res.y; v.z += res.z; v.w += res.w;

            float s  = wsum(v.x + v.y + v.z + v.w);
            float ss = wsum(v.x * v.x + v.y * v.y + v.z * v.z + v.w * v.w);
            float mu = s * (1.f / 128.f);
            float var = ss * (1.f / 128.f) - mu * mu;
            float rs = rsqrtf(var + 1e-5f);

            float4 o2;
            o2.x = g4.x * (v.x - mu) * rs + b4.x;
            o2.y = g4.y * (v.y - mu) * rs + b4.y;
            o2.z = g4.z * (v.z - mu) * rs + b4.z;
            o2.w = g4.w * (v.w - mu) * rs + b4.w;
            *reinterpret_cast<float4*>(out + (r0 + e) * NDM + 4 * lane) = o2;
        }
        __syncwarp();
    }
}

// ---------------- launch ----------------
extern "C" void kernel_launch(void* const* d_in, const int* in_sizes, int n_in,
                              void* d_out, int out_size) {
    const int*   eidx = (const int*)d_in[0];
    const float* ef   = (const float*)d_in[1];
    const float* iQ   = (const float*)d_in[2];
    const float* iK   = (const float*)d_in[3];
    const float* iV   = (const float*)d_in[4];
    const float* WQ   = (const float*)d_in[5];
    const float* WK   = (const float*)d_in[6];
    const float* WV   = (const float*)d_in[7];
    const float* WE   = (const float*)d_in[8];
    const float* Wfc  = (const float*)d_in[9];
    const float* gam  = (const float*)d_in[10];
    const float* bet  = (const float*)d_in[11];

    float* out = (float*)d_out;
    float* attn_out = out + (long long)NB * NN * NDM;

    const size_t SMEM = (size_t)SMEM_FLOATS * sizeof(float);
    static int smem_set = 0;
    if (!smem_set) {
        cudaFuncSetAttribute(proj_kernel, cudaFuncAttributeMaxDynamicSharedMemorySize, (int)SMEM);
        cudaFuncSetAttribute(edge_kernel, cudaFuncAttributeMaxDynamicSharedMemorySize, (int)SMEM);
        cudaFuncSetAttribute(finalize_kernel, cudaFuncAttributeMaxDynamicSharedMemorySize, (int)SMEM);
        cudaFuncSetAttribute(edge_tc_kernel, cudaFuncAttributeMaxDynamicSharedMemorySize,
                             SMEM_EDGE_BYTES);
        smem_set = 1;
    }

    void *np, *dp, *qp, *kp, *vp;
    cudaGetSymbolAddress(&np, g_num);
    cudaGetSymbolAddress(&dp, g_den);
    cudaGetSymbolAddress(&qp, g_Q);
    cudaGetSymbolAddress(&kp, g_K);
    cudaGetSymbolAddress(&vp, g_V);

    cudaMemsetAsync(np, 0, sizeof(g_num));
    cudaMemsetAsync(dp, 0, sizeof(g_den));

    dim3 blk(256);
    const int GRID = 296;
    proj_kernel<<<GRID, blk, SMEM>>>(iQ, WQ, (float*)qp, NB * NN);
    proj_kernel<<<GRID, blk, SMEM>>>(iK, WK, (float*)kp, NB * NN);
    proj_kernel<<<GRID, blk, SMEM>>>(iV, WV, (float*)vp, NB * NN);
    // exactly one of these two does the edge work, depending on which cubin
    // (arch-specific vs generic) the runtime selected; the other is a no-op.
    edge_tc_kernel<<<148, 512, SMEM_EDGE_BYTES>>>(eidx, ef, WE, attn_out);
    edge_kernel<<<GRID, blk, SMEM>>>(eidx, ef, WE, attn_out);
    finalize_kernel<<<GRID, blk, SMEM>>>(iQ, Wfc, gam, bet, out);
}

// round 11
// speedup vs baseline: 1.4988x; 1.4988x over previous
#include <cuda_runtime.h>
#include <cuda_bf16.h>
#include <cstdint>

#define NB 4
#define NN 16384
#define NEG 131072
#define NH 4
#define NDK 32
#define NDM 128
#define EPB 8  // rows per warp block in scalar gemm kernels

#define TILE_M 128
#define NTILES (NB * NEG / TILE_M)   // 4096 edge tiles
#define PTILES (NB * NN / TILE_M)    // 512 proj tiles per matrix

// tcgen05 only legal in arch-specific (sm_103a) device compilation passes.
#if defined(__CUDA_ARCH__) && (__CUDA_ARCH__ == 1030) && \
    (defined(__CUDA_ARCH_FEAT_SM103_ALL) || defined(__CUDA_ARCH_SPECIFIC__))
#define HAS_TCGEN05 1
#else
#define HAS_TCGEN05 0
#endif

// ---------------- device scratch (no allocs allowed) ----------------
__device__ float g_Q[NB * NN * NDM];
__device__ float g_K[NB * NN * NDM];
__device__ float g_V[NB * NN * NDM];
__device__ float g_num[NB * NN * NDM];
__device__ float g_den[NB * NN * NH];

// ---------------- packed f32x2 helpers ----------------
__device__ __forceinline__ unsigned long long pack2(float a, float b) {
    unsigned long long r;
    asm("mov.b64 %0, {%1,%2};" : "=l"(r) : "f"(a), "f"(b));
    return r;
}
__device__ __forceinline__ void unpack2(unsigned long long v, float& a, float& b) {
    asm("mov.b64 {%0,%1}, %2;" : "=f"(a), "=f"(b) : "l"(v));
}
__device__ __forceinline__ unsigned long long fma2(unsigned long long a, unsigned long long b,
                                                   unsigned long long c) {
    unsigned long long r;
    asm("fma.rn.f32x2 %0, %1, %2, %3;" : "=l"(r) : "l"(a), "l"(b), "l"(c));
    return r;
}

__device__ __forceinline__ float wsum(float v) {
#pragma unroll
    for (int o = 16; o; o >>= 1) v += __shfl_xor_sync(0xffffffffu, v, o);
    return v;
}

// ---------------- edge tc kernel smem layout (R8 proven) ----------------
#define SM_A_HI 0
#define SM_A_LO 32768
#define SM_B_HI 65536
#define SM_B_LO 98304
#define SM_TPTR 131072
#define SM_MBAR 131080
#define SM_ATTN 131088                    // float4[2][128]  (4096B)
#define SM_ROWS (SM_ATTN + 4096)          // int2[2][128]    (2048B)
#define SM_PART (SM_ROWS + 2048)          // float4[128]     (2048B) score partials
#define SMEM_EDGE_BYTES (SM_PART + 2048)

// ---------------- proj tc kernel smem layout ----------------
#define PR_B_HI 0
#define PR_B_LO 32768
#define PR_A_HI(s) (65536 + (s) * 65536)
#define PR_A_LO(s) (98304 + (s) * 65536)
#define PR_TPTR 196608
#define PR_MBAR 196616                    // 2 mbarriers at +0, +8
#define SMEM_PROJ_BYTES 196640

#if HAS_TCGEN05
// ---------------- tcgen05 / mbarrier PTX helpers (arch-specific only) ----------------
__device__ __forceinline__ uint32_t smem_u32(const void* p) {
    uint32_t a;
    asm("{ .reg .u64 t; cvta.to.shared.u64 t, %1; cvt.u32.u64 %0, t; }" : "=r"(a) : "l"(p));
    return a;
}
__device__ __forceinline__ uint32_t elect_one_pred() {
    uint32_t pred;
    asm volatile(
        "{\n\t.reg .pred p;\n\telect.sync _|p, 0xFFFFFFFF;\n\tselp.b32 %0, 1, 0, p;\n\t}"
        : "=r"(pred));
    return pred;
}

#define TCG_ALLOC(smem_addr, ncols) \
    asm volatile("tcgen05.alloc.cta_group::1.sync.aligned.shared::cta.b32 [%0], %1;" \
                 :: "r"((uint32_t)(smem_addr)), "r"((uint32_t)(ncols)) : "memory")
#define TCG_DEALLOC(tmem, ncols) \
    asm volatile("tcgen05.dealloc.cta_group::1.sync.aligned.b32 %0, %1;" :: "r"(tmem), "r"((uint32_t)(ncols)))
#define TCG_COMMIT(mbar) \
    asm volatile("tcgen05.commit.cta_group::1.mbarrier::arrive::one.shared::cluster.b64 [%0];" \
                 :: "r"((uint32_t)(mbar)) : "memory")
#define TCG_WAIT_LD() asm volatile("tcgen05.wait::ld.sync.aligned;" ::: "memory")
#define TCG_FENCE_AFTER() asm volatile("tcgen05.fence::after_thread_sync;" ::: "memory")
#define FENCE_ASYNC_SHARED() asm volatile("fence.proxy.async.shared::cta;" ::: "memory")

#define MBAR_INIT(mbar, cnt) \
    asm volatile("mbarrier.init.shared.b64 [%0], %1;" :: "r"((uint32_t)(mbar)), "r"((uint32_t)(cnt)) : "memory")

#define MBAR_WAIT_PARITY(mbar, parity) do {                                              \
    uint32_t _m = (uint32_t)(mbar);                                                      \
    uint32_t _p = (uint32_t)(parity);                                                    \
    asm volatile(                                                                        \
        "{\n\t.reg .pred P1;\n\t"                                                        \
        "WAIT_LOOP_%=:\n\t"                                                              \
        "mbarrier.try_wait.parity.acquire.cta.shared::cta.b64 P1, [%0], %1, 0x989680;\n\t" \
        "@P1 bra.uni WAIT_DONE_%=;\n\t"                                                  \
        "bra.uni WAIT_LOOP_%=;\n\t"                                                      \
        "WAIT_DONE_%=:\n\t}"                                                             \
        :: "r"(_m), "r"(_p) : "memory");                                                 \
} while (0)

#define TCG_LD_X32(r, addr)                                                              \
    asm volatile(                                                                        \
        "tcgen05.ld.sync.aligned.32x32b.x32.b32 "                                        \
        "{%0, %1, %2, %3, %4, %5, %6, %7, "                                              \
        " %8, %9, %10, %11, %12, %13, %14, %15, "                                        \
        " %16, %17, %18, %19, %20, %21, %22, %23, "                                      \
        " %24, %25, %26, %27, %28, %29, %30, %31}, [%32];"                               \
        : "=r"((r)[0]),  "=r"((r)[1]),  "=r"((r)[2]),  "=r"((r)[3]),                     \
          "=r"((r)[4]),  "=r"((r)[5]),  "=r"((r)[6]),  "=r"((r)[7]),                     \
          "=r"((r)[8]),  "=r"((r)[9]),  "=r"((r)[10]), "=r"((r)[11]),                    \
          "=r"((r)[12]), "=r"((r)[13]), "=r"((r)[14]), "=r"((r)[15]),                    \
          "=r"((r)[16]), "=r"((r)[17]), "=r"((r)[18]), "=r"((r)[19]),                    \
          "=r"((r)[20]), "=r"((r)[21]), "=r"((r)[22]), "=r"((r)[23]),                    \
          "=r"((r)[24]), "=r"((r)[25]), "=r"((r)[26]), "=r"((r)[27]),                    \
          "=r"((r)[28]), "=r"((r)[29]), "=r"((r)[30]), "=r"((r)[31])                     \
        : "r"(addr))

__device__ __forceinline__ void mma_f16_ss(uint32_t d, uint64_t ad, uint64_t bd,
                                           uint32_t idesc, uint32_t en) {
    asm volatile(
        "{\n\t.reg .pred p;\n\tsetp.ne.u32 p, %5, 0;\n\t"
        "tcgen05.mma.cta_group::1.kind::f16 [%0], %1, %2, %3, {%4, %4, %4, %4}, p;\n\t}"
        :: "r"(d), "l"(ad), "l"(bd), "r"(idesc), "r"(0u), "r"(en) : "memory");
}

__device__ __forceinline__ void red_add_v4(float* p, float a, float b, float c, float d) {
    asm volatile("red.global.add.v4.f32 [%0], {%1, %2, %3, %4};"
                 :: "l"(p), "f"(a), "f"(b), "f"(c), "f"(d) : "memory");
}

// blocked SW128 atom layout for 128x128 bf16 tile (atom = 8 rows x 64 cols = 1024B,
// 16 atom-rows x 2 atom-cols, atom_off = ar + ac*16) — extension of test_mma_iter.
__device__ __forceinline__ uint32_t ab_off(int row, int col) {
    uint32_t byte = (uint32_t)(((row >> 3) + (col >> 6) * 16) * 1024 + (row & 7) * 128 + (col & 63) * 2);
    return byte ^ ((byte >> 3) & 0x70);
}
__device__ __forceinline__ uint64_t mk_desc(uint32_t a) {
    return (uint64_t(2) << 61) | (uint64_t(1) << 46) | (uint64_t(64) << 32) |
           (uint64_t(1) << 16) | ((a >> 4) & 0x3FFF);
}

// idesc: F32 accum, BF16 a/b, N=128, M=128 (cg1)
#define MMA_IDESC 0x8200490u

__device__ __forceinline__ unsigned short bf16b(__nv_bfloat16 h) {
    return __bfloat16_as_ushort(h);
}

// stage 128x128 fp32 rows -> split bf16 (hi/lo) in blocked-atom layout
__device__ __forceinline__ void load_A_tile(const float* __restrict__ X, long long rowbase,
                                            char* sm, int a_hi, int a_lo, int t0, int stride) {
    for (int i = t0; i < 4096; i += stride) {
        int r = i >> 5;
        int c4 = (i & 31) << 2;
        float4 x = *reinterpret_cast<const float4*>(X + (rowbase + r) * NDM + c4);
        __nv_bfloat16 hx = __float2bfloat16(x.x), hy = __float2bfloat16(x.y);
        __nv_bfloat16 hz = __float2bfloat16(x.z), hw = __float2bfloat16(x.w);
        __nv_bfloat16 lx = __float2bfloat16(x.x - __bfloat162float(hx));
        __nv_bfloat16 ly = __float2bfloat16(x.y - __bfloat162float(hy));
        __nv_bfloat16 lz = __float2bfloat16(x.z - __bfloat162float(hz));
        __nv_bfloat16 lw = __float2bfloat16(x.w - __bfloat162float(hw));
        uint32_t off = ab_off(r, c4);
        uint2 hv = make_uint2((uint32_t)bf16b(hx) | ((uint32_t)bf16b(hy) << 16),
                              (uint32_t)bf16b(hz) | ((uint32_t)bf16b(hw) << 16));
        uint2 lv = make_uint2((uint32_t)bf16b(lx) | ((uint32_t)bf16b(ly) << 16),
                              (uint32_t)bf16b(lz) | ((uint32_t)bf16b(lw) << 16));
        *reinterpret_cast<uint2*>(sm + a_hi + off) = hv;
        *reinterpret_cast<uint2*>(sm + a_lo + off) = lv;
    }
}

// stage W (cols head-permuted, transposed) as split-bf16 B tile
__device__ __forceinline__ void stage_B_tile(const float* __restrict__ W, char* sm,
                                             int b_hi, int b_lo, int t0, int stride) {
    for (int i = t0; i < NDM * NDM; i += stride) {
        int n = i >> 7, k = i & 127;
        float w = W[k * NDM + ((n & 3) * NDK + (n >> 2))];
        __nv_bfloat16 h = __float2bfloat16(w);
        __nv_bfloat16 l = __float2bfloat16(w - __bfloat162float(h));
        uint32_t off = ab_off(n, k);
        *reinterpret_cast<unsigned short*>(sm + b_hi + off) = bf16b(h);
        *reinterpret_cast<unsigned short*>(sm + b_lo + off) = bf16b(l);
    }
}

// 3-pass split-bf16 MMA over K=128 (Ah*Bh + Ah*Bl + Al*Bh)
__device__ __forceinline__ void issue_mma(uint32_t d_tmem, uint32_t smb,
                                          int a_hi, int a_lo, int b_hi, int b_lo,
                                          uint32_t mbar) {
    uint64_t ah = mk_desc(smb + a_hi), al = mk_desc(smb + a_lo);
    uint64_t bh = mk_desc(smb + b_hi), bl = mk_desc(smb + b_lo);
    uint64_t Ad[3] = {ah, ah, al};
    uint64_t Bd[3] = {bh, bl, bh};
#pragma unroll
    for (int p = 0; p < 3; ++p) {
#pragma unroll
        for (int s = 0; s < 8; ++s) {
            uint32_t off = (s < 4) ? (uint32_t)(2 * s) : (uint32_t)(1024 + 2 * (s - 4));
            mma_f16_ss(d_tmem, Ad[p] + off, Bd[p] + off, MMA_IDESC, !(p == 0 && s == 0));
        }
    }
    TCG_COMMIT(mbar);
}
#endif  // HAS_TCGEN05

// ---------------- edge tensor-core kernel (R8 structure, arch-specific cubin only) ----------------
__global__ __launch_bounds__(512, 1) void edge_tc_kernel(const int* __restrict__ eidx,
                                                         const float* __restrict__ ef,
                                                         const float* __restrict__ WE,
                                                         float* __restrict__ attn_out) {
#if HAS_TCGEN05
    extern __shared__ char sm[];
    uint32_t smb = smem_u32(sm);
    const int tid = threadIdx.x, wid = tid >> 5, lane = tid & 31;
    const float scale = 0.1767766952966369f;  // 1/sqrt(32)

    if (wid == 0) TCG_ALLOC(smb + SM_TPTR, 512);

    stage_B_tile(WE, sm, SM_B_HI, SM_B_LO, tid, 512);
    if (tid == 0) MBAR_INIT(smb + SM_MBAR, 1);
    __syncthreads();

    uint32_t tmem;
    asm volatile("ld.shared.b32 %0, [%1];" : "=r"(tmem) : "r"(smb + SM_TPTR));

    // prologue: stage A(tile0) with all threads, launch MMA(0) -> D0
    {
        int t0 = blockIdx.x;
        long long rb = (long long)(t0 >> 10) * NEG + (long long)(t0 & 1023) * TILE_M;
        load_A_tile(ef, rb, sm, SM_A_HI, SM_A_LO, tid, 512);
    }
    FENCE_ASYNC_SHARED();
    __syncthreads();
    if (wid == 8 && elect_one_pred())
        issue_mma(tmem, smb, SM_A_HI, SM_A_LO, SM_B_HI, SM_B_LO, smb + SM_MBAR);

    int i = 0;
    uint32_t phase = 0;
    for (int t = blockIdx.x; t < NTILES; t += gridDim.x, ++i) {
        MBAR_WAIT_PARITY(smb + SM_MBAR, phase);
        phase ^= 1;
        TCG_FENCE_AFTER();

        const int b = t >> 10;
        const int e0 = (t & 1023) * TILE_M;
        const int tn = t + gridDim.x;

        float s0 = 0.f, s1 = 0.f, s2 = 0.f, s3 = 0.f;
        int qrow = 0;

        if (wid < 8) {
            // ---- score: warps 0-3 cols [0,64), warps 4-7 cols [64,128) ----
            const uint32_t Dcur = tmem + (uint32_t)((i & 1) * 128);
            const int sub = wid & 3, half = wid >> 2;
            const int m = sub * 32 + lane;
            const int e = e0 + m;
            const int src = eidx[(b * 2) * NEG + e];
            const int tgt = eidx[(b * 2 + 1) * NEG + e];
            qrow = b * NN + src;
            const int krow = b * NN + tgt;
#pragma unroll 1
            for (int c = 0; c < 2; ++c) {
                const int col = half * 64 + c * 32;
                uint32_t rE[32];
                TCG_LD_X32(rE, Dcur + (uint32_t)col);
                TCG_WAIT_LD();
                const float4* qp = reinterpret_cast<const float4*>(g_Q + (long long)qrow * NDM + col);
                const float4* kp = reinterpret_cast<const float4*>(g_K + (long long)krow * NDM + col);
#pragma unroll
                for (int j = 0; j < 8; ++j) {
                    float4 q4 = qp[j], k4 = kp[j];
                    s0 += q4.x * k4.x * __uint_as_float(rE[4 * j + 0]);
                    s1 += q4.y * k4.y * __uint_as_float(rE[4 * j + 1]);
                    s2 += q4.z * k4.z * __uint_as_float(rE[4 * j + 2]);
                    s3 += q4.w * k4.w * __uint_as_float(rE[4 * j + 3]);
                }
            }
            if (half)
                reinterpret_cast<float4*>(sm + SM_PART)[m] = make_float4(s0, s1, s2, s3);
            else
                reinterpret_cast<int2*>(sm + SM_ROWS + (i & 1) * 1024)[m] = make_int2(qrow, krow);
        } else if (tn < NTILES) {
            // ---- warps 8-15: stage A(t+1) ----
            long long rb = (long long)(tn >> 10) * NEG + (long long)(tn & 1023) * TILE_M;
            load_A_tile(ef, rb, sm, SM_A_HI, SM_A_LO, tid - 256, 256);
        }

        FENCE_ASYNC_SHARED();
        __syncthreads();

        if (wid < 4) {
            // ---- finalize: combine partials, exp/clip, den-red, attn stores ----
            const int m = wid * 32 + lane;
            float4 p = reinterpret_cast<const float4*>(sm + SM_PART)[m];
            s0 += p.x; s1 += p.y; s2 += p.z; s3 += p.w;
            float a0 = __expf(fminf(fmaxf(s0 * scale, -5.f), 5.f));
            float a1 = __expf(fminf(fmaxf(s1 * scale, -5.f), 5.f));
            float a2 = __expf(fminf(fmaxf(s2 * scale, -5.f), 5.f));
            float a3 = __expf(fminf(fmaxf(s3 * scale, -5.f), 5.f));

            red_add_v4(g_den + (long long)qrow * NH, a0, a1, a2, a3);
            if (b == NB - 1) {
                const int e = e0 + m;
                attn_out[e] = a0;
                attn_out[NEG + e] = a1;
                attn_out[2 * NEG + e] = a2;
                attn_out[3 * NEG + e] = a3;
            }
            reinterpret_cast<float4*>(sm + SM_ATTN + (i & 1) * 2048)[m] = make_float4(a0, a1, a2, a3);
        }
        __syncthreads();

        if (tn < NTILES && wid == 8 && elect_one_pred())
            issue_mma(tmem + (uint32_t)(((i + 1) & 1) * 128), smb,
                      SM_A_HI, SM_A_LO, SM_B_HI, SM_B_LO, smb + SM_MBAR);

        // ---- scatter: warp w handles edges [8w, 8w+8), one float4 per lane per edge ----
#pragma unroll
        for (int k = 0; k < 8; ++k) {
            const int m = wid * 8 + k;
            float4 a4 = reinterpret_cast<const float4*>(sm + SM_ATTN + (i & 1) * 2048)[m];
            int2 rw = reinterpret_cast<const int2*>(sm + SM_ROWS + (i & 1) * 1024)[m];
            float4 v4 = reinterpret_cast<const float4*>(g_V + (long long)rw.y * NDM)[lane];
            red_add_v4(g_num + (long long)rw.x * NDM + 4 * lane,
                       a4.x * v4.x, a4.y * v4.y, a4.z * v4.z, a4.w * v4.w);
        }
    }

    __syncthreads();
    if (wid == 0) TCG_DEALLOC(tmem, 512);
#else
    (void)eidx; (void)ef; (void)WE; (void)attn_out;
#endif
}

// ---------------- proj tensor-core kernel: Q/K/V projections (arch-specific only) ----------------
// CTAs [0,50) -> Q, [50,99) -> K, [99,148) -> V. Each CTA stages its W once and
// loops its tile range with double-buffered A + TMEM D.
__global__ __launch_bounds__(512, 1) void proj_tc_kernel(const float* __restrict__ iQ,
                                                         const float* __restrict__ iK,
                                                         const float* __restrict__ iV,
                                                         const float* __restrict__ WQ,
                                                         const float* __restrict__ WK,
                                                         const float* __restrict__ WV,
                                                         float* __restrict__ oQ,
                                                         float* __restrict__ oK,
                                                         float* __restrict__ oV) {
#if HAS_TCGEN05
    extern __shared__ char sm[];
    uint32_t smb = smem_u32(sm);
    const int tid = threadIdx.x, wid = tid >> 5, lane = tid & 31;

    int which, lb, nb;
    if (blockIdx.x < 50)      { which = 0; lb = blockIdx.x;      nb = 50; }
    else if (blockIdx.x < 99) { which = 1; lb = blockIdx.x - 50; nb = 49; }
    else                      { which = 2; lb = blockIdx.x - 99; nb = 49; }
    const float* X = which == 0 ? iQ : (which == 1 ? iK : iV);
    const float* W = which == 0 ? WQ : (which == 1 ? WK : WV);
    float* Y       = which == 0 ? oQ : (which == 1 ? oK : oV);

    if (wid == 0) TCG_ALLOC(smb + PR_TPTR, 256);

    stage_B_tile(W, sm, PR_B_HI, PR_B_LO, tid, 512);
    if (tid < 2) MBAR_INIT(smb + PR_MBAR + tid * 8, 1);
    __syncthreads();

    uint32_t tmem;
    asm volatile("ld.shared.b32 %0, [%1];" : "=r"(tmem) : "r"(smb + PR_TPTR));

    // prologue: stage A(first tile) -> buf0, issue MMA -> D0
    load_A_tile(X, (long long)lb * TILE_M, sm, PR_A_HI(0), PR_A_LO(0), tid, 512);
    FENCE_ASYNC_SHARED();
    __syncthreads();
    if (wid == 0 && elect_one_pred())
        issue_mma(tmem, smb, PR_A_HI(0), PR_A_LO(0), PR_B_HI, PR_B_LO, smb + PR_MBAR);

    const int sub = wid & 3, qtr = wid >> 2;   // 16 warps: 4 subpartitions x 4 col-quarters
    const int m = sub * 32 + lane;

    uint32_t ph[2] = {0, 0};
    int i = 0;
    for (int t = lb; t < PTILES; t += nb, ++i) {
        const int s = i & 1;
        const int tn = t + nb;

        // stage A(next) into other buffer while MMA(t) runs
        if (tn < PTILES)
            load_A_tile(X, (long long)tn * TILE_M, sm, PR_A_HI(1 - s), PR_A_LO(1 - s), tid, 512);
        FENCE_ASYNC_SHARED();
        __syncthreads();
        if (tn < PTILES && wid == 0 && elect_one_pred())
            issue_mma(tmem + (uint32_t)((1 - s) * 128), smb, PR_A_HI(1 - s), PR_A_LO(1 - s),
                      PR_B_HI, PR_B_LO, smb + PR_MBAR + (1 - s) * 8);

        // wait for D(t), read, store
        MBAR_WAIT_PARITY(smb + PR_MBAR + s * 8, ph[s]);
        ph[s] ^= 1;
        TCG_FENCE_AFTER();

        uint32_t rD[32];
        TCG_LD_X32(rD, tmem + (uint32_t)(s * 128 + qtr * 32));
        TCG_WAIT_LD();

        float* yp = Y + ((long long)t * TILE_M + m) * NDM + qtr * 32;
#pragma unroll
        for (int j = 0; j < 8; ++j) {
            float4 o = make_float4(__uint_as_float(rD[4 * j + 0]), __uint_as_float(rD[4 * j + 1]),
                                   __uint_as_float(rD[4 * j + 2]), __uint_as_float(rD[4 * j + 3]));
            *reinterpret_cast<float4*>(yp + 4 * j) = o;
        }
    }

    __syncthreads();
    if (wid == 0) TCG_DEALLOC(tmem, 256);
#else
    (void)iQ; (void)iK; (void)iV; (void)WQ; (void)WK; (void)WV; (void)oQ; (void)oK; (void)oV;
#endif
}

// ---------------- scalar warp GEMM pieces ----------------
__device__ __forceinline__ void warp_block_gemm8(const float* __restrict__ xs,
                                                 const float* __restrict__ Ws, int lane,
                                                 float4* __restrict__ out) {
    unsigned long long a01[EPB], a23[EPB];
#pragma unroll
    for (int e = 0; e < EPB; ++e) { a01[e] = 0ull; a23[e] = 0ull; }
#pragma unroll 2
    for (int g = 0; g < 32; ++g) {
        const float* wp = Ws + (4 * g) * NDM + 4 * lane;
        float4 w0 = *reinterpret_cast<const float4*>(wp);
        float4 w1 = *reinterpret_cast<const float4*>(wp + NDM);
        float4 w2 = *reinterpret_cast<const float4*>(wp + 2 * NDM);
        float4 w3 = *reinterpret_cast<const float4*>(wp + 3 * NDM);
        unsigned long long w0a = pack2(w0.x, w0.y), w0b = pack2(w0.z, w0.w);
        unsigned long long w1a = pack2(w1.x, w1.y), w1b = pack2(w1.z, w1.w);
        unsigned long long w2a = pack2(w2.x, w2.y), w2b = pack2(w2.z, w2.w);
        unsigned long long w3a = pack2(w3.x, w3.y), w3b = pack2(w3.z, w3.w);
#pragma unroll
        for (int e = 0; e < EPB; ++e) {
            float4 x = *reinterpret_cast<const float4*>(xs + e * NDM + 4 * g);
            unsigned long long xx;
            xx = pack2(x.x, x.x); a01[e] = fma2(xx, w0a, a01[e]); a23[e] = fma2(xx, w0b, a23[e]);
            xx = pack2(x.y, x.y); a01[e] = fma2(xx, w1a, a01[e]); a23[e] = fma2(xx, w1b, a23[e]);
            xx = pack2(x.z, x.z); a01[e] = fma2(xx, w2a, a01[e]); a23[e] = fma2(xx, w2b, a23[e]);
            xx = pack2(x.w, x.w); a01[e] = fma2(xx, w3a, a01[e]); a23[e] = fma2(xx, w3b, a23[e]);
        }
    }
#pragma unroll
    for (int e = 0; e < EPB; ++e) {
        unpack2(a01[e], out[e].x, out[e].y);
        unpack2(a23[e], out[e].z, out[e].w);
    }
}

__device__ __forceinline__ void load_W_headperm(const float* __restrict__ W, float* Wr) {
    for (int idx = threadIdx.x; idx < NDM * NDM; idx += blockDim.x) {
        int c = idx & (NDM - 1);
        int d = c >> 2, h = c & 3;
        Wr[idx] = W[(idx - c) + h * NDK + d];
    }
}

#define SMEM_FLOATS (NDM * NDM + 8 * EPB * NDM)

// ---------------- scalar edge kernel (active only in generic cubin) ----------------
__global__ __launch_bounds__(256, 2) void edge_kernel(const int* __restrict__ eidx,
                                                      const float* __restrict__ ef,
                                                      const float* __restrict__ WE,
                                                      float* __restrict__ attn_out) {
#if HAS_TCGEN05
    (void)eidx; (void)ef; (void)WE; (void)attn_out;  // tc kernel does the work
#else
    extern __shared__ float smf[];
    float* Wr = smf;
    load_W_headperm(WE, Wr);
    __syncthreads();

    const int lane = threadIdx.x & 31;
    const int warp = threadIdx.x >> 5;
    float* xs = smf + NDM * NDM + warp * EPB * NDM;
    int gw = blockIdx.x * (blockDim.x >> 5) + warp;
    int nw = gridDim.x * (blockDim.x >> 5);
    const float scale = 0.1767766952966369f;  // 1/sqrt(32)

    const int ngroups = NB * NEG / EPB;
    const int gpb = NEG / EPB;

    for (int gi = gw; gi < ngroups; gi += nw) {
        int b = gi / gpb;
        int e0 = (gi - b * gpb) * EPB;

        int src_l = 0, tgt_l = 0;
        if (lane < EPB) {
            src_l = eidx[(b * 2) * NEG + e0 + lane];
            tgt_l = eidx[(b * 2 + 1) * NEG + e0 + lane];
        }

        long long t0 = (long long)b * NEG + e0;
#pragma unroll
        for (int e = 0; e < EPB; ++e) {
            float4 x4 = *reinterpret_cast<const float4*>(ef + (t0 + e) * NDM + 4 * lane);
            *reinterpret_cast<float4*>(xs + e * NDM + 4 * lane) = x4;
        }
        __syncwarp();

        float4 Ev[EPB];
        warp_block_gemm8(xs, Wr, lane, Ev);

#pragma unroll
        for (int c = 0; c < 2; ++c) {
            float4 q[4], k4[4], v4[4];
            int qr[4];
#pragma unroll
            for (int ii = 0; ii < 4; ++ii) {
                int e = c * 4 + ii;
                int src = __shfl_sync(0xffffffffu, src_l, e);
                int tgt = __shfl_sync(0xffffffffu, tgt_l, e);
                qr[ii] = b * NN + src;
                int kr = b * NN + tgt;
                q[ii]  = *reinterpret_cast<const float4*>(g_Q + (long long)qr[ii] * NDM + 4 * lane);
                k4[ii] = *reinterpret_cast<const float4*>(g_K + (long long)kr * NDM + 4 * lane);
                v4[ii] = *reinterpret_cast<const float4*>(g_V + (long long)kr * NDM + 4 * lane);
            }
#pragma unroll
            for (int ii = 0; ii < 4; ++ii) {
                int e = c * 4 + ii;
                float4 E = Ev[e];
                float p0 = wsum(q[ii].x * k4[ii].x * E.x);
                float p1 = wsum(q[ii].y * k4[ii].y * E.y);
                float p2 = wsum(q[ii].z * k4[ii].z * E.z);
                float p3 = wsum(q[ii].w * k4[ii].w * E.w);

                float a0 = __expf(fminf(fmaxf(p0 * scale, -5.f), 5.f));
                float a1 = __expf(fminf(fmaxf(p1 * scale, -5.f), 5.f));
                float a2 = __expf(fminf(fmaxf(p2 * scale, -5.f), 5.f));
                float a3 = __expf(fminf(fmaxf(p3 * scale, -5.f), 5.f));

                float* np = g_num + (long long)qr[ii] * NDM + 4 * lane;
                atomicAdd(np + 0, a0 * v4[ii].x);
                atomicAdd(np + 1, a1 * v4[ii].y);
                atomicAdd(np + 2, a2 * v4[ii].z);
                atomicAdd(np + 3, a3 * v4[ii].w);
                if (lane < 4) {
                    float aa = lane == 0 ? a0 : (lane == 1 ? a1 : (lane == 2 ? a2 : a3));
                    atomicAdd(g_den + qr[ii] * NH + lane, aa);
                    if (b == NB - 1) attn_out[(long long)lane * NEG + e0 + e] = aa;
                }
            }
        }
        __syncwarp();
    }
#endif
}

// ---------------- scalar projections (active only in generic cubin) ----------------
__global__ __launch_bounds__(256, 2) void proj_kernel(const float* __restrict__ X,
                                                      const float* __restrict__ W,
                                                      float* __restrict__ Y, int nrows) {
#if HAS_TCGEN05
    (void)X; (void)W; (void)Y; (void)nrows;  // proj_tc does the work
#else
    extern __shared__ float smf[];
    float* Wr = smf;
    load_W_headperm(W, Wr);
    __syncthreads();

    const int lane = threadIdx.x & 31;
    const int warp = threadIdx.x >> 5;
    float* xs = smf + NDM * NDM + warp * EPB * NDM;
    int gw = blockIdx.x * (blockDim.x >> 5) + warp;
    int nw = gridDim.x * (blockDim.x >> 5);
    const int ngroups = nrows / EPB;

    for (int gi = gw; gi < ngroups; gi += nw) {
        long long r0 = (long long)gi * EPB;
#pragma unroll
        for (int e = 0; e < EPB; ++e) {
            float4 x4 = *reinterpret_cast<const float4*>(X + (r0 + e) * NDM + 4 * lane);
            *reinterpret_cast<float4*>(xs + e * NDM + 4 * lane) = x4;
        }
        __syncwarp();
        float4 y[EPB];
        warp_block_gemm8(xs, Wr, lane, y);
#pragma unroll
        for (int e = 0; e < EPB; ++e)
            *reinterpret_cast<float4*>(Y + (r0 + e) * NDM + 4 * lane) = y[e];
        __syncwarp();
    }
#endif
}

// ---------------- kernel 3: num/den -> @W_fc -> +residual -> layernorm (both cubins) ----------------
__global__ __launch_bounds__(256, 2) void finalize_kernel(const float* __restrict__ residual,
                                                          const float* __restrict__ Wfc,
                                                          const float* __restrict__ gamma,
                                                          const float* __restrict__ beta,
                                                          float* __restrict__ out) {
    extern __shared__ float smf[];
    float* Wr = smf;
    for (int idx = threadIdx.x; idx < NDM * NDM; idx += blockDim.x) {
        int jp = idx >> 7, m = idx & 127;
        int srow = (jp & 3) * NDK + (jp >> 2);
        Wr[idx] = Wfc[srow * NDM + m];
    }
    __syncthreads();

    const int lane = threadIdx.x & 31;
    const int warp = threadIdx.x >> 5;
    float* xs = smf + NDM * NDM + warp * EPB * NDM;
    int gw = blockIdx.x * (blockDim.x >> 5) + warp;
    int nw = gridDim.x * (blockDim.x >> 5);

    float4 g4 = *reinterpret_cast<const float4*>(gamma + 4 * lane);
    float4 b4 = *reinterpret_cast<const float4*>(beta + 4 * lane);
    const int ngroups = NB * NN / EPB;

    for (int gi = gw; gi < ngroups; gi += nw) {
        long long r0 = (long long)gi * EPB;
#pragma unroll
        for (int e = 0; e < EPB; ++e) {
            float4 num4 = *reinterpret_cast<const float4*>(g_num + (r0 + e) * NDM + 4 * lane);
            float4 den4 = *reinterpret_cast<const float4*>(g_den + (r0 + e) * NH);
            float4 o;
            o.x = num4.x / (den4.x + 1e-8f);
            o.y = num4.y / (den4.y + 1e-8f);
            o.z = num4.z / (den4.z + 1e-8f);
            o.w = num4.w / (den4.w + 1e-8f);
            *reinterpret_cast<float4*>(xs + e * NDM + 4 * lane) = o;
        }
        __syncwarp();

        float4 y[EPB];
        warp_block_gemm8(xs, Wr, lane, y);

#pragma unroll
        for (int e = 0; e < EPB; ++e) {
            float4 res = *reinterpret_cast<const float4*>(residual + (r0 + e) * NDM + 4 * lane);
            float4 v = y[e];
            v.x += res.x; v.y += res.y; v.z += res.z; v.w += res.w;

            float s  = wsum(v.x + v.y + v.z + v.w);
            float ss = wsum(v.x * v.x + v.y * v.y + v.z * v.z + v.w * v.w);
            float mu = s * (1.f / 128.f);
            float var = ss * (1.f / 128.f) - mu * mu;
            float rs = rsqrtf(var + 1e-5f);

            float4 o2;
            o2.x = g4.x * (v.x - mu) * rs + b4.x;
            o2.y = g4.y * (v.y - mu) * rs + b4.y;
            o2.z = g4.z * (v.z - mu) * rs + b4.z;
            o2.w = g4.w * (v.w - mu) * rs + b4.w;
            *reinterpret_cast<float4*>(out + (r0 + e) * NDM + 4 * lane) = o2;
        }
        __syncwarp();
    }
}

// ---------------- launch ----------------
extern "C" void kernel_launch(void* const* d_in, const int* in_sizes, int n_in,
                              void* d_out, int out_size) {
    const int*   eidx = (const int*)d_in[0];
    const float* ef   = (const float*)d_in[1];
    const float* iQ   = (const float*)d_in[2];
    const float* iK   = (const float*)d_in[3];
    const float* iV   = (const float*)d_in[4];
    const float* WQ   = (const float*)d_in[5];
    const float* WK   = (const float*)d_in[6];
    const float* WV   = (const float*)d_in[7];
    const float* WE   = (const float*)d_in[8];
    const float* Wfc  = (const float*)d_in[9];
    const float* gam  = (const float*)d_in[10];
    const float* bet  = (const float*)d_in[11];

    float* out = (float*)d_out;
    float* attn_out = out + (long long)NB * NN * NDM;

    const size_t SMEM = (size_t)SMEM_FLOATS * sizeof(float);
    static int smem_set = 0;
    if (!smem_set) {
        cudaFuncSetAttribute(proj_kernel, cudaFuncAttributeMaxDynamicSharedMemorySize, (int)SMEM);
        cudaFuncSetAttribute(edge_kernel, cudaFuncAttributeMaxDynamicSharedMemorySize, (int)SMEM);
        cudaFuncSetAttribute(finalize_kernel, cudaFuncAttributeMaxDynamicSharedMemorySize, (int)SMEM);
        cudaFuncSetAttribute(edge_tc_kernel, cudaFuncAttributeMaxDynamicSharedMemorySize,
                             SMEM_EDGE_BYTES);
        cudaFuncSetAttribute(proj_tc_kernel, cudaFuncAttributeMaxDynamicSharedMemorySize,
                             SMEM_PROJ_BYTES);
        smem_set = 1;
    }

    void *np, *dp, *qp, *kp, *vp;
    cudaGetSymbolAddress(&np, g_num);
    cudaGetSymbolAddress(&dp, g_den);
    cudaGetSymbolAddress(&qp, g_Q);
    cudaGetSymbolAddress(&kp, g_K);
    cudaGetSymbolAddress(&vp, g_V);

    cudaMemsetAsync(np, 0, sizeof(g_num));
    cudaMemsetAsync(dp, 0, sizeof(g_den));

    dim3 blk(256);
    const int GRID = 296;
    // tensor path (no-ops in generic cubin)
    proj_tc_kernel<<<148, 512, SMEM_PROJ_BYTES>>>(iQ, iK, iV, WQ, WK, WV,
                                                  (float*)qp, (float*)kp, (float*)vp);
    // scalar path (no-ops in arch-specific cubin)
    proj_kernel<<<GRID, blk, SMEM>>>(iQ, WQ, (float*)qp, NB * NN);
    proj_kernel<<<GRID, blk, SMEM>>>(iK, WK, (float*)kp, NB * NN);
    proj_kernel<<<GRID, blk, SMEM>>>(iV, WV, (float*)vp, NB * NN);
    // edge: exactly one of these does the work per cubin
    edge_tc_kernel<<<148, 512, SMEM_EDGE_BYTES>>>(eidx, ef, WE, attn_out);
    edge_kernel<<<GRID, blk, SMEM>>>(eidx, ef, WE, attn_out);
    finalize_kernel<<<GRID, blk, SMEM>>>(iQ, Wfc, gam, bet, out);
}